// round 1
// baseline (speedup 1.0000x reference)
#include <cuda_runtime.h>
#include <stdint.h>

#define N_NODES 50000
#define N_EDGES 800000
#define IN_F    256
#define OUT_F   64

// Scratch for h = x @ W  (50000 x 64 fp32 = 12.8 MB) — device global (no allocs allowed)
__device__ float g_h[N_NODES * OUT_F];

// ---------------------------------------------------------------------------
// Kernel 1: h = x @ W.   Warp-per-node, lane owns 2 output columns.
// W staged in shared as two 128x64 k-tiles (32 KB each).
// ---------------------------------------------------------------------------
#define NODES_PER_WARP 4
#define GEMM_BLOCK 256
#define GEMM_WARPS (GEMM_BLOCK / 32)
#define NODES_PER_ROUND (GEMM_WARPS * NODES_PER_WARP)   // 32

__global__ void __launch_bounds__(GEMM_BLOCK) gemm_kernel(
    const float* __restrict__ x, const float* __restrict__ w)
{
    __shared__ float ws[128 * 64];   // 32 KB k-tile of W

    const int warp = threadIdx.x >> 5;
    const int lane = threadIdx.x & 31;

    for (int base = blockIdx.x * NODES_PER_ROUND; base < N_NODES;
         base += gridDim.x * NODES_PER_ROUND)
    {
        float acc[NODES_PER_WARP][2];
        #pragma unroll
        for (int r = 0; r < NODES_PER_WARP; r++) { acc[r][0] = 0.f; acc[r][1] = 0.f; }

        #pragma unroll
        for (int tile = 0; tile < 2; tile++) {
            __syncthreads();
            // load W[tile*128 .. tile*128+127][0..63] into shared (float4)
            {
                const float4* wsrc = (const float4*)(w + tile * 128 * OUT_F);
                float4* wdst = (float4*)ws;
                #pragma unroll
                for (int i = threadIdx.x; i < 128 * OUT_F / 4; i += GEMM_BLOCK)
                    wdst[i] = wsrc[i];
            }
            __syncthreads();

            #pragma unroll
            for (int r = 0; r < NODES_PER_WARP; r++) {
                const int node = base + warp * NODES_PER_WARP + r;
                if (node >= N_NODES) continue;
                const float4* xr = (const float4*)(x + (size_t)node * IN_F + tile * 128);
                float a0 = acc[r][0], a1 = acc[r][1];
                #pragma unroll
                for (int kk = 0; kk < 32; kk++) {
                    const float4 xv = __ldg(&xr[kk]);        // broadcast across warp
                    const float* wr = ws + (kk * 4) * OUT_F + lane * 2;
                    float2 w0 = *(const float2*)(wr + 0 * OUT_F);
                    a0 = fmaf(xv.x, w0.x, a0); a1 = fmaf(xv.x, w0.y, a1);
                    float2 w1 = *(const float2*)(wr + 1 * OUT_F);
                    a0 = fmaf(xv.y, w1.x, a0); a1 = fmaf(xv.y, w1.y, a1);
                    float2 w2 = *(const float2*)(wr + 2 * OUT_F);
                    a0 = fmaf(xv.z, w2.x, a0); a1 = fmaf(xv.z, w2.y, a1);
                    float2 w3 = *(const float2*)(wr + 3 * OUT_F);
                    a0 = fmaf(xv.w, w3.x, a0); a1 = fmaf(xv.w, w3.y, a1);
                }
                acc[r][0] = a0; acc[r][1] = a1;
            }
        }

        #pragma unroll
        for (int r = 0; r < NODES_PER_WARP; r++) {
            const int node = base + warp * NODES_PER_WARP + r;
            if (node < N_NODES)
                *(float2*)(g_h + (size_t)node * OUT_F + lane * 2) =
                    make_float2(acc[r][0], acc[r][1]);
        }
    }
}

// ---------------------------------------------------------------------------
// Kernel 2: out[n][f] = bias[f]   (out is poisoned; must init before atomics)
// ---------------------------------------------------------------------------
__global__ void init_kernel(float* __restrict__ out, const float* __restrict__ bias)
{
    const int t = blockIdx.x * blockDim.x + threadIdx.x;
    const int total4 = N_NODES * OUT_F / 4;
    if (t < total4) {
        const float4* b4 = (const float4*)bias;
        ((float4*)out)[t] = __ldg(&b4[t & 15]);
    }
}

// ---------------------------------------------------------------------------
// Kernel 3: scatter — out[dst] += w_e * h[src].  16 threads per edge,
// each thread does one float4 slice via red.global.add.v4.f32 (sm_90+).
// ---------------------------------------------------------------------------
__global__ void scatter_kernel(const float* __restrict__ ew,
                               const int* __restrict__ esrc,
                               const int* __restrict__ edst,
                               float* __restrict__ out)
{
    const int t = blockIdx.x * blockDim.x + threadIdx.x;
    const int e = t >> 4;
    if (e >= N_EDGES) return;
    const int c = (t & 15) << 2;

    const int src = __ldg(&esrc[e]);
    const int dst = __ldg(&edst[e]);
    const float w = __ldg(&ew[e]);

    const float4 hv = *(const float4*)(g_h + (size_t)src * OUT_F + c);
    float* p = out + (size_t)dst * OUT_F + c;
    asm volatile("red.global.add.v4.f32 [%0], {%1, %2, %3, %4};"
                 :: "l"(p), "f"(hv.x * w), "f"(hv.y * w), "f"(hv.z * w), "f"(hv.w * w)
                 : "memory");
}

// ---------------------------------------------------------------------------
// inputs (metadata order): x, weight, bias, edge_weight, edge_src, edge_dst
// ---------------------------------------------------------------------------
extern "C" void kernel_launch(void* const* d_in, const int* in_sizes, int n_in,
                              void* d_out, int out_size)
{
    const float* x      = (const float*)d_in[0];
    const float* weight = (const float*)d_in[1];
    const float* bias   = (const float*)d_in[2];
    const float* ew     = (const float*)d_in[3];
    const int*   esrc   = (const int*)d_in[4];
    const int*   edst   = (const int*)d_in[5];
    float* out = (float*)d_out;

    // 1) h = x @ W
    gemm_kernel<<<592, GEMM_BLOCK>>>(x, weight);

    // 2) out = bias
    {
        const int total4 = N_NODES * OUT_F / 4;
        init_kernel<<<(total4 + 255) / 256, 256>>>(out, bias);
    }

    // 3) scatter-add over edges
    {
        const long long threads = (long long)N_EDGES * 16;
        const int blk = 256;
        const int grid = (int)((threads + blk - 1) / blk);
        scatter_kernel<<<grid, blk>>>(ew, esrc, edst, out);
    }
}

// round 2
// speedup vs baseline: 2.5937x; 2.5937x over previous
#include <cuda_runtime.h>
#include <stdint.h>

#define N_NODES 50000
#define N_EDGES 800000
#define IN_F    256
#define OUT_F   64

// Scratch for h = x @ W  (50000 x 64 fp32 = 12.8 MB) — device global (no allocs allowed)
__device__ float g_h[N_NODES * OUT_F];

// ---------------------------------------------------------------------------
// Kernel 1: h = x @ W  as register-blocked SGEMM.
//   M = N_NODES (50000), N = 64, K = 256
//   Block tile: BM=128 x BN=64, BK=16. 256 threads, each owns an 8x4 tile.
//   Double-buffered smem, global->reg prefetch, one __syncthreads per k-tile.
// ---------------------------------------------------------------------------
#define BM 128
#define BN 64
#define BK 16
#define TM 8
#define TN 4
#define XS_STRIDE (BM + 4)     // padded row stride (floats), keeps float4 alignment

__global__ void __launch_bounds__(256, 3) gemm_kernel(
    const float* __restrict__ x, const float* __restrict__ w)
{
    __shared__ __align__(16) float xs[2][BK][XS_STRIDE];  // x tile, transposed: xs[k][m]
    __shared__ __align__(16) float ws[2][BK][BN];         // w tile: ws[k][n]

    const int tid = threadIdx.x;
    const int tx = tid & 15;          // 0..15 -> col group (n = tx*4)
    const int ty = tid >> 4;          // 0..15 -> row group (m = ty*8)
    const int block_m = blockIdx.x * BM;

    // x-tile loader: tile is BM x BK floats = 512 float4; each thread loads 2.
    const int xrow0 = tid >> 2;              // 0..63
    const int xrow1 = xrow0 + 64;            // 64..127
    const int xkc   = (tid & 3) << 2;        // k-offset within tile: 0,4,8,12
    // clamp rows so the last (partial) block stays in-bounds; results guarded at store
    const int gr0 = min(block_m + xrow0, N_NODES - 1);
    const int gr1 = min(block_m + xrow1, N_NODES - 1);
    const float* xp0 = x + (size_t)gr0 * IN_F + xkc;
    const float* xp1 = x + (size_t)gr1 * IN_F + xkc;

    // w-tile loader: tile is BK x BN floats = 256 float4; each thread loads 1.
    const int wrow = tid >> 4;               // 0..15 (k within tile)
    const int wcol = (tid & 15) << 2;        // 0..60 step 4
    const float* wp = w + (size_t)wrow * OUT_F + wcol;

    float acc[TM][TN];
    #pragma unroll
    for (int i = 0; i < TM; i++)
        #pragma unroll
        for (int j = 0; j < TN; j++) acc[i][j] = 0.f;

    // ---- prologue: fetch tile 0 and stage into buffer 0 ----
    float4 xf0 = *(const float4*)(xp0);
    float4 xf1 = *(const float4*)(xp1);
    float4 wf  = *(const float4*)(wp);

    xs[0][xkc + 0][xrow0] = xf0.x; xs[0][xkc + 1][xrow0] = xf0.y;
    xs[0][xkc + 2][xrow0] = xf0.z; xs[0][xkc + 3][xrow0] = xf0.w;
    xs[0][xkc + 0][xrow1] = xf1.x; xs[0][xkc + 1][xrow1] = xf1.y;
    xs[0][xkc + 2][xrow1] = xf1.z; xs[0][xkc + 3][xrow1] = xf1.w;
    *(float4*)&ws[0][wrow][wcol] = wf;
    __syncthreads();

    const int NKT = IN_F / BK;   // 16 k-tiles

    #pragma unroll 1
    for (int kt = 0; kt < NKT; kt++) {
        const int buf = kt & 1;

        // prefetch next tile global -> registers
        if (kt + 1 < NKT) {
            const int k0 = (kt + 1) * BK;
            xf0 = *(const float4*)(xp0 + k0);
            xf1 = *(const float4*)(xp1 + k0);
            wf  = *(const float4*)(wp + (size_t)k0 * OUT_F);
        }

        // compute on current buffer
        #pragma unroll
        for (int k = 0; k < BK; k++) {
            float a[TM], b[TN];
            *(float4*)&a[0] = *(const float4*)&xs[buf][k][ty * TM + 0];
            *(float4*)&a[4] = *(const float4*)&xs[buf][k][ty * TM + 4];
            *(float4*)&b[0] = *(const float4*)&ws[buf][k][tx * TN];
            #pragma unroll
            for (int i = 0; i < TM; i++)
                #pragma unroll
                for (int j = 0; j < TN; j++)
                    acc[i][j] = fmaf(a[i], b[j], acc[i][j]);
        }

        // stage prefetched tile into the other buffer
        if (kt + 1 < NKT) {
            const int nb = buf ^ 1;
            xs[nb][xkc + 0][xrow0] = xf0.x; xs[nb][xkc + 1][xrow0] = xf0.y;
            xs[nb][xkc + 2][xrow0] = xf0.z; xs[nb][xkc + 3][xrow0] = xf0.w;
            xs[nb][xkc + 0][xrow1] = xf1.x; xs[nb][xkc + 1][xrow1] = xf1.y;
            xs[nb][xkc + 2][xrow1] = xf1.z; xs[nb][xkc + 3][xrow1] = xf1.w;
            *(float4*)&ws[nb][wrow][wcol] = wf;
            __syncthreads();
        }
    }

    // ---- epilogue: store 8x4 tile ----
    #pragma unroll
    for (int i = 0; i < TM; i++) {
        const int node = block_m + ty * TM + i;
        if (node < N_NODES) {
            float4 v = make_float4(acc[i][0], acc[i][1], acc[i][2], acc[i][3]);
            *(float4*)(g_h + (size_t)node * OUT_F + tx * TN) = v;
        }
    }
}

// ---------------------------------------------------------------------------
// Kernel 2: out[n][f] = bias[f]   (out is poisoned; must init before atomics)
// ---------------------------------------------------------------------------
__global__ void init_kernel(float* __restrict__ out, const float* __restrict__ bias)
{
    const int t = blockIdx.x * blockDim.x + threadIdx.x;
    const int total4 = N_NODES * OUT_F / 4;
    if (t < total4) {
        const float4* b4 = (const float4*)bias;
        ((float4*)out)[t] = __ldg(&b4[t & 15]);
    }
}

// ---------------------------------------------------------------------------
// Kernel 3: scatter — out[dst] += w_e * h[src].  16 threads per edge,
// each thread does one float4 slice via red.global.add.v4.f32 (sm_90+).
// ---------------------------------------------------------------------------
__global__ void scatter_kernel(const float* __restrict__ ew,
                               const int* __restrict__ esrc,
                               const int* __restrict__ edst,
                               float* __restrict__ out)
{
    const int t = blockIdx.x * blockDim.x + threadIdx.x;
    const int e = t >> 4;
    if (e >= N_EDGES) return;
    const int c = (t & 15) << 2;

    const int src = __ldg(&esrc[e]);
    const int dst = __ldg(&edst[e]);
    const float w = __ldg(&ew[e]);

    const float4 hv = *(const float4*)(g_h + (size_t)src * OUT_F + c);
    float* p = out + (size_t)dst * OUT_F + c;
    asm volatile("red.global.add.v4.f32 [%0], {%1, %2, %3, %4};"
                 :: "l"(p), "f"(hv.x * w), "f"(hv.y * w), "f"(hv.z * w), "f"(hv.w * w)
                 : "memory");
}

// ---------------------------------------------------------------------------
// inputs (metadata order): x, weight, bias, edge_weight, edge_src, edge_dst
// ---------------------------------------------------------------------------
extern "C" void kernel_launch(void* const* d_in, const int* in_sizes, int n_in,
                              void* d_out, int out_size)
{
    const float* x      = (const float*)d_in[0];
    const float* weight = (const float*)d_in[1];
    const float* bias   = (const float*)d_in[2];
    const float* ew     = (const float*)d_in[3];
    const int*   esrc   = (const int*)d_in[4];
    const int*   edst   = (const int*)d_in[5];
    float* out = (float*)d_out;

    // 1) h = x @ W   (register-blocked SGEMM)
    {
        const int grid = (N_NODES + BM - 1) / BM;   // 391
        gemm_kernel<<<grid, 256>>>(x, weight);
    }

    // 2) out = bias
    {
        const int total4 = N_NODES * OUT_F / 4;
        init_kernel<<<(total4 + 255) / 256, 256>>>(out, bias);
    }

    // 3) scatter-add over edges
    {
        const long long threads = (long long)N_EDGES * 16;
        const int blk = 256;
        const int grid = (int)((threads + blk - 1) / blk);
        scatter_kernel<<<grid, blk>>>(ew, esrc, edst, out);
    }
}